// round 6
// baseline (speedup 1.0000x reference)
#include <cuda_runtime.h>
#include <cuda_bf16.h>
#include <math.h>

// Problem constants (fixed by the dataset)
#define NNODES 50000
#define NEDGES 800000
#define INF    128
#define HID    64
#define NCLS   40

// ---------------- scratch (static __device__ globals; no allocation) -------
__device__ int   g_deg[NNODES];
__device__ int   g_fill[NNODES];
__device__ int   g_rowptr[NNODES + 1];
__device__ float g_dinv[NNODES];
__device__ int   g_col[NEDGES];
__device__ float g_bufA[(size_t)NNODES * HID];
__device__ float g_bufB[(size_t)NNODES * HID];

// ---------------- graph preprocessing --------------------------------------

__global__ void init_kernel(int* __restrict__ deg, int* __restrict__ fill, int n) {
    int i = blockIdx.x * blockDim.x + threadIdx.x;
    if (i < n) { deg[i] = 1; fill[i] = 0; }   // deg starts at 1 (self loop)
}

__global__ void hist_kernel(int* __restrict__ deg, const int* __restrict__ dst, int E) {
    int e = blockIdx.x * blockDim.x + threadIdx.x;
    if (e < E) atomicAdd(&deg[dst[e]], 1);
}

// Single-block exclusive scan of (deg-1) -> row_ptr, plus dinv = rsqrt(deg).
__global__ void scan_kernel(const int* __restrict__ deg, int* __restrict__ rowptr,
                            float* __restrict__ dinv, int n, int E) {
    __shared__ int ssum[1024];
    int tid = threadIdx.x;
    int chunk = (n + 1023) / 1024;
    int base = tid * chunk;

    int s = 0;
    for (int i = 0; i < chunk; i++) {
        int idx = base + i;
        if (idx < n) s += deg[idx] - 1;
    }
    ssum[tid] = s;
    __syncthreads();
    // Hillis-Steele inclusive scan
    for (int off = 1; off < 1024; off <<= 1) {
        int v = (tid >= off) ? ssum[tid - off] : 0;
        __syncthreads();
        ssum[tid] += v;
        __syncthreads();
    }
    int run = (tid > 0) ? ssum[tid - 1] : 0;   // exclusive prefix of this thread's chunk
    for (int i = 0; i < chunk; i++) {
        int idx = base + i;
        if (idx < n) {
            rowptr[idx] = run;
            run += deg[idx] - 1;
            dinv[idx] = rsqrtf((float)deg[idx]);
        }
    }
    if (tid == 0) rowptr[n] = E;
}

__global__ void build_kernel(const int* __restrict__ src, const int* __restrict__ dst,
                             const int* __restrict__ rowptr, int* __restrict__ fill,
                             int* __restrict__ colv, int E) {
    int e = blockIdx.x * blockDim.x + threadIdx.x;
    if (e < E) {
        int d = dst[e];
        int pos = rowptr[d] + atomicAdd(&fill[d], 1);
        colv[pos] = src[e];
    }
}

// ---------------- dense GEMM: C[M,N] = A[M,K] @ W[K,N],  N <= 64 -----------
// BM=64, 256 threads, each thread computes a 4x4 tile. W fully resident in
// smem (zero-padded to 64 cols). A staged in BK=32 chunks, stored TRANSPOSED
// (As[k][row]) so the inner loop is two LDS.128 per k (A frag broadcast
// across the 16 col-threads, W frag conflict-free).
template <int K>
__global__ void gemm_kernel(const float* __restrict__ A, const float* __restrict__ W,
                            float* __restrict__ C, int M, int N) {
    __shared__ float Ws[K][64];
    __shared__ float As[32][68];   // +4 pad, keeps float4 alignment (68*4=272)

    int tid = threadIdx.x;
    int rowBase = blockIdx.x * 64;

    // load W (zero-pad cols >= N)
    for (int i = tid; i < K * 64; i += 256) {
        int k = i >> 6, c = i & 63;
        Ws[k][c] = (c < N) ? W[k * N + c] : 0.0f;
    }

    int tx = tid & 15;          // -> 4 output cols
    int ty = tid >> 4;          // -> 4 output rows
    float acc[4][4] = {};

    for (int k0 = 0; k0 < K; k0 += 32) {
        __syncthreads();
        // stage A chunk transposed: 64 rows x 32 k, float4 loads
        #pragma unroll
        for (int i = tid; i < (64 * 32) / 4; i += 256) {
            int idx = i * 4;
            int r = idx >> 5;        // row within tile
            int kk = idx & 31;       // k within chunk
            int grow = rowBase + r;
            float4 v = make_float4(0.f, 0.f, 0.f, 0.f);
            if (grow < M) v = *(const float4*)&A[(size_t)grow * K + k0 + kk];
            As[kk + 0][r] = v.x;
            As[kk + 1][r] = v.y;
            As[kk + 2][r] = v.z;
            As[kk + 3][r] = v.w;
        }
        __syncthreads();

        #pragma unroll
        for (int k = 0; k < 32; k++) {
            float4 a = *(const float4*)&As[k][ty * 4];
            float4 w = *(const float4*)&Ws[k0 + k][tx * 4];
            acc[0][0] += a.x * w.x; acc[0][1] += a.x * w.y; acc[0][2] += a.x * w.z; acc[0][3] += a.x * w.w;
            acc[1][0] += a.y * w.x; acc[1][1] += a.y * w.y; acc[1][2] += a.y * w.z; acc[1][3] += a.y * w.w;
            acc[2][0] += a.z * w.x; acc[2][1] += a.z * w.y; acc[2][2] += a.z * w.z; acc[2][3] += a.z * w.w;
            acc[3][0] += a.w * w.x; acc[3][1] += a.w * w.y; acc[3][2] += a.w * w.z; acc[3][3] += a.w * w.w;
        }
    }

    #pragma unroll
    for (int i = 0; i < 4; i++) {
        int r = rowBase + ty * 4 + i;
        if (r < M) {
            #pragma unroll
            for (int j = 0; j < 4; j++) {
                int c = tx * 4 + j;
                if (c < N) C[(size_t)r * N + c] = acc[i][j];
            }
        }
    }
}

// ---------------- aggregation (gather, one warp per node) ------------------
// out[v] = dv * ( sum_{s in nbr(v)} dinv[s]*H[s]  +  dv*H[v] ) + bias
template <int F, bool RELU>
__global__ void agg_kernel(const float* __restrict__ H, float* __restrict__ out,
                           const int* __restrict__ rowptr, const int* __restrict__ colv,
                           const float* __restrict__ dinv, const float* __restrict__ bias,
                           int n) {
    int w = (blockIdx.x * blockDim.x + threadIdx.x) >> 5;
    int lane = threadIdx.x & 31;
    if (w >= n) return;

    const bool act = (lane * 2) < F;      // F=64: all lanes; F=40: lanes 0..19
    float2 acc = make_float2(0.f, 0.f);
    int beg = rowptr[w];
    int end = rowptr[w + 1];
    float dv = dinv[w];

    for (int e = beg; e < end; e++) {
        int s = colv[e];
        float ws = dinv[s];
        if (act) {
            float2 hv = *(const float2*)&H[(size_t)s * F + lane * 2];
            acc.x += ws * hv.x;
            acc.y += ws * hv.y;
        }
    }

    if (act) {
        // self loop
        float2 hv = *(const float2*)&H[(size_t)w * F + lane * 2];
        acc.x += dv * hv.x;
        acc.y += dv * hv.y;
        float b0 = bias[lane * 2 + 0];
        float b1 = bias[lane * 2 + 1];
        float o0 = dv * acc.x + b0;
        float o1 = dv * acc.y + b1;
        if (RELU) { o0 = fmaxf(o0, 0.f); o1 = fmaxf(o1, 0.f); }
        float2 ov = make_float2(o0, o1);
        *(float2*)&out[(size_t)w * F + lane * 2] = ov;
    }
}

// ---------------- launcher --------------------------------------------------

extern "C" void kernel_launch(void* const* d_in, const int* in_sizes, int n_in,
                              void* d_out, int out_size) {
    const float* x  = (const float*)d_in[0];
    const int*   ei = (const int*)d_in[1];
    const float* W1 = (const float*)d_in[2];
    const float* b1 = (const float*)d_in[3];
    const float* W2 = (const float*)d_in[4];
    const float* b2 = (const float*)d_in[5];
    const float* W3 = (const float*)d_in[6];
    const float* b3 = (const float*)d_in[7];
    float* out = (float*)d_out;

    const int n = in_sizes[0] / INF;     // 50000
    const int E = in_sizes[1] / 2;       // 800000

    int *deg, *fill, *rowptr, *colv;
    float *dinvp, *bufA, *bufB;
    cudaGetSymbolAddress((void**)&deg,    g_deg);
    cudaGetSymbolAddress((void**)&fill,   g_fill);
    cudaGetSymbolAddress((void**)&rowptr, g_rowptr);
    cudaGetSymbolAddress((void**)&colv,   g_col);
    cudaGetSymbolAddress((void**)&dinvp,  g_dinv);
    cudaGetSymbolAddress((void**)&bufA,   g_bufA);
    cudaGetSymbolAddress((void**)&bufB,   g_bufB);

    const int* srcp = ei;
    const int* dstp = ei + E;

    // graph preprocessing (once, reused by all 3 layers)
    init_kernel<<<(n + 255) / 256, 256>>>(deg, fill, n);
    hist_kernel<<<(E + 255) / 256, 256>>>(deg, dstp, E);
    scan_kernel<<<1, 1024>>>(deg, rowptr, dinvp, n, E);
    build_kernel<<<(E + 255) / 256, 256>>>(srcp, dstp, rowptr, fill, colv, E);

    const int gemmBlocks = (n + 63) / 64;
    const int aggBlocks  = (n * 32 + 255) / 256;

    // layer 1: 128 -> 64, relu
    gemm_kernel<INF><<<gemmBlocks, 256>>>(x, W1, bufA, n, HID);
    agg_kernel<HID, true><<<aggBlocks, 256>>>(bufA, bufB, rowptr, colv, dinvp, b1, n);

    // layer 2: 64 -> 64, relu
    gemm_kernel<HID><<<gemmBlocks, 256>>>(bufB, W2, bufA, n, HID);
    agg_kernel<HID, true><<<aggBlocks, 256>>>(bufA, bufB, rowptr, colv, dinvp, b2, n);

    // layer 3: 64 -> 40, no relu
    gemm_kernel<HID><<<gemmBlocks, 256>>>(bufB, W3, bufA, n, NCLS);
    agg_kernel<NCLS, false><<<aggBlocks, 256>>>(bufA, out, rowptr, colv, dinvp, b3, n);
}

// round 7
// speedup vs baseline: 1.0245x; 1.0245x over previous
#include <cuda_runtime.h>
#include <cuda_fp16.h>
#include <math.h>

// Problem constants (fixed by the dataset)
#define NNODES 50000
#define NEDGES 800000
#define INF    128
#define HID    64
#define NCLS   40

// ---------------- scratch (static __device__ globals; no allocation) -------
__device__ int    g_deg[NNODES];
__device__ int    g_fill[NNODES];
__device__ int    g_rowptr[NNODES + 1];
__device__ float  g_dinv[NNODES];
__device__ int2   g_edge[NEDGES];                 // {src, __float_as_int(dinv[src])}
__device__ __half g_bufH[(size_t)NNODES * HID];   // GEMM outputs (fp16, gathered by agg)
__device__ float  g_bufF[(size_t)NNODES * HID];   // agg outputs (fp32, GEMM inputs)

// ---------------- graph preprocessing --------------------------------------

__global__ void init_kernel(int* __restrict__ deg, int* __restrict__ fill, int n) {
    int i = blockIdx.x * blockDim.x + threadIdx.x;
    if (i < n) { deg[i] = 1; fill[i] = 0; }   // deg starts at 1 (self loop)
}

__global__ void hist_kernel(int* __restrict__ deg, const int* __restrict__ dst, int E) {
    int e = blockIdx.x * blockDim.x + threadIdx.x;
    if (e < E) atomicAdd(&deg[dst[e]], 1);
}

// Single-block exclusive scan of (deg-1) -> row_ptr, plus dinv = rsqrt(deg).
__global__ void scan_kernel(const int* __restrict__ deg, int* __restrict__ rowptr,
                            float* __restrict__ dinv, int n, int E) {
    __shared__ int ssum[1024];
    int tid = threadIdx.x;
    int chunk = (n + 1023) / 1024;
    int base = tid * chunk;

    int s = 0;
    for (int i = 0; i < chunk; i++) {
        int idx = base + i;
        if (idx < n) s += deg[idx] - 1;
    }
    ssum[tid] = s;
    __syncthreads();
    for (int off = 1; off < 1024; off <<= 1) {
        int v = (tid >= off) ? ssum[tid - off] : 0;
        __syncthreads();
        ssum[tid] += v;
        __syncthreads();
    }
    int run = (tid > 0) ? ssum[tid - 1] : 0;
    for (int i = 0; i < chunk; i++) {
        int idx = base + i;
        if (idx < n) {
            rowptr[idx] = run;
            run += deg[idx] - 1;
            dinv[idx] = rsqrtf((float)deg[idx]);
        }
    }
    if (tid == 0) rowptr[n] = E;
}

// Build CSR-by-dst; fold dinv[src] into the edge record so the per-layer agg
// never does the random dinv lookup (it was a 32B-sector read per edge, 3x).
__global__ void build_kernel(const int* __restrict__ src, const int* __restrict__ dst,
                             const int* __restrict__ rowptr, int* __restrict__ fill,
                             const float* __restrict__ dinv, int2* __restrict__ edges, int E) {
    int e = blockIdx.x * blockDim.x + threadIdx.x;
    if (e < E) {
        int d = dst[e];
        int s = src[e];
        int pos = rowptr[d] + atomicAdd(&fill[d], 1);
        edges[pos] = make_int2(s, __float_as_int(dinv[s]));
    }
}

// ---------------- dense GEMM: C[M,N] = A[M,K] @ W[K,N],  N <= 64 -----------
// BM=64, 256 threads, 4x4 tile per thread. W resident in smem (zero-padded to
// 64 cols). A staged in BK=32 chunks transposed for LDS.128 broadcast reads.
// Output stored as fp16 (agg gathers it; halves gather traffic).
template <int K>
__global__ void gemm_kernel(const float* __restrict__ A, const float* __restrict__ W,
                            __half* __restrict__ C, int M, int N) {
    __shared__ float Ws[K][64];
    __shared__ float As[32][68];   // +4 pad keeps float4 alignment

    int tid = threadIdx.x;
    int rowBase = blockIdx.x * 64;

    for (int i = tid; i < K * 64; i += 256) {
        int k = i >> 6, c = i & 63;
        Ws[k][c] = (c < N) ? W[k * N + c] : 0.0f;
    }

    int tx = tid & 15;          // -> 4 output cols
    int ty = tid >> 4;          // -> 4 output rows
    float acc[4][4] = {};

    for (int k0 = 0; k0 < K; k0 += 32) {
        __syncthreads();
        #pragma unroll
        for (int i = tid; i < (64 * 32) / 4; i += 256) {
            int idx = i * 4;
            int r = idx >> 5;
            int kk = idx & 31;
            int grow = rowBase + r;
            float4 v = make_float4(0.f, 0.f, 0.f, 0.f);
            if (grow < M) v = *(const float4*)&A[(size_t)grow * K + k0 + kk];
            As[kk + 0][r] = v.x;
            As[kk + 1][r] = v.y;
            As[kk + 2][r] = v.z;
            As[kk + 3][r] = v.w;
        }
        __syncthreads();

        #pragma unroll
        for (int k = 0; k < 32; k++) {
            float4 a = *(const float4*)&As[k][ty * 4];
            float4 w = *(const float4*)&Ws[k0 + k][tx * 4];
            acc[0][0] += a.x * w.x; acc[0][1] += a.x * w.y; acc[0][2] += a.x * w.z; acc[0][3] += a.x * w.w;
            acc[1][0] += a.y * w.x; acc[1][1] += a.y * w.y; acc[1][2] += a.y * w.z; acc[1][3] += a.y * w.w;
            acc[2][0] += a.z * w.x; acc[2][1] += a.z * w.y; acc[2][2] += a.z * w.z; acc[2][3] += a.z * w.w;
            acc[3][0] += a.w * w.x; acc[3][1] += a.w * w.y; acc[3][2] += a.w * w.z; acc[3][3] += a.w * w.w;
        }
    }

    // epilogue: fp16, half2 stores (N is even; col groups of 4 never straddle N)
    #pragma unroll
    for (int i = 0; i < 4; i++) {
        int r = rowBase + ty * 4 + i;
        int c0 = tx * 4;
        if (r < M && c0 < N) {
            __half2 h01 = __floats2half2_rn(acc[i][0], acc[i][1]);
            __half2 h23 = __floats2half2_rn(acc[i][2], acc[i][3]);
            *(__half2*)&C[(size_t)r * N + c0 + 0] = h01;
            *(__half2*)&C[(size_t)r * N + c0 + 2] = h23;
        }
    }
}

// ---------------- aggregation (gather, one warp per node) ------------------
// out[v] = dv * ( sum_{s in nbr(v)} dinv[s]*H[s]  +  dv*H[v] ) + bias
// H is fp16 (half2 per lane -> 128B/row gather for F=64), accumulate fp32.
template <int F, bool RELU>
__global__ void agg_kernel(const __half2* __restrict__ H, float* __restrict__ out,
                           const int* __restrict__ rowptr, const int2* __restrict__ edges,
                           const float* __restrict__ dinv, const float* __restrict__ bias,
                           int n) {
    int w = (blockIdx.x * blockDim.x + threadIdx.x) >> 5;
    int lane = threadIdx.x & 31;
    if (w >= n) return;

    const bool act = lane < (F / 2);      // F=64: all lanes; F=40: lanes 0..19
    float ax = 0.f, ay = 0.f;
    int beg = rowptr[w];
    int end = rowptr[w + 1];
    float dv = dinv[w];

    int e = beg;
    // unrolled x2 for MLP: two independent gathers in flight
    for (; e + 1 < end; e += 2) {
        int2 e0 = edges[e];
        int2 e1 = edges[e + 1];
        float w0 = __int_as_float(e0.y);
        float w1 = __int_as_float(e1.y);
        if (act) {
            float2 h0 = __half22float2(H[(size_t)e0.x * (F / 2) + lane]);
            float2 h1 = __half22float2(H[(size_t)e1.x * (F / 2) + lane]);
            ax += w0 * h0.x + w1 * h1.x;
            ay += w0 * h0.y + w1 * h1.y;
        }
    }
    if (e < end) {
        int2 e0 = edges[e];
        float w0 = __int_as_float(e0.y);
        if (act) {
            float2 h0 = __half22float2(H[(size_t)e0.x * (F / 2) + lane]);
            ax += w0 * h0.x;
            ay += w0 * h0.y;
        }
    }

    if (act) {
        // self loop
        float2 hv = __half22float2(H[(size_t)w * (F / 2) + lane]);
        ax += dv * hv.x;
        ay += dv * hv.y;
        float o0 = dv * ax + bias[lane * 2 + 0];
        float o1 = dv * ay + bias[lane * 2 + 1];
        if (RELU) { o0 = fmaxf(o0, 0.f); o1 = fmaxf(o1, 0.f); }
        *(float2*)&out[(size_t)w * F + lane * 2] = make_float2(o0, o1);
    }
}

// ---------------- launcher --------------------------------------------------

extern "C" void kernel_launch(void* const* d_in, const int* in_sizes, int n_in,
                              void* d_out, int out_size) {
    const float* x  = (const float*)d_in[0];
    const int*   ei = (const int*)d_in[1];
    const float* W1 = (const float*)d_in[2];
    const float* b1 = (const float*)d_in[3];
    const float* W2 = (const float*)d_in[4];
    const float* b2 = (const float*)d_in[5];
    const float* W3 = (const float*)d_in[6];
    const float* b3 = (const float*)d_in[7];
    float* out = (float*)d_out;

    const int n = in_sizes[0] / INF;     // 50000
    const int E = in_sizes[1] / 2;       // 800000

    int *deg, *fill, *rowptr;
    int2* edges;
    float *dinvp, *bufF;
    __half* bufH;
    cudaGetSymbolAddress((void**)&deg,    g_deg);
    cudaGetSymbolAddress((void**)&fill,   g_fill);
    cudaGetSymbolAddress((void**)&rowptr, g_rowptr);
    cudaGetSymbolAddress((void**)&edges,  g_edge);
    cudaGetSymbolAddress((void**)&dinvp,  g_dinv);
    cudaGetSymbolAddress((void**)&bufH,   g_bufH);
    cudaGetSymbolAddress((void**)&bufF,   g_bufF);

    const int* srcp = ei;
    const int* dstp = ei + E;

    // graph preprocessing (once, reused by all 3 layers)
    init_kernel<<<(n + 255) / 256, 256>>>(deg, fill, n);
    hist_kernel<<<(E + 255) / 256, 256>>>(deg, dstp, E);
    scan_kernel<<<1, 1024>>>(deg, rowptr, dinvp, n, E);
    build_kernel<<<(E + 255) / 256, 256>>>(srcp, dstp, rowptr, fill, dinvp, edges, E);

    const int gemmBlocks = (n + 63) / 64;
    const int aggBlocks  = (n * 32 + 255) / 256;

    // layer 1: 128 -> 64, relu
    gemm_kernel<INF><<<gemmBlocks, 256>>>(x, W1, bufH, n, HID);
    agg_kernel<HID, true><<<aggBlocks, 256>>>((const __half2*)bufH, bufF, rowptr, edges, dinvp, b1, n);

    // layer 2: 64 -> 64, relu
    gemm_kernel<HID><<<gemmBlocks, 256>>>(bufF, W2, bufH, n, HID);
    agg_kernel<HID, true><<<aggBlocks, 256>>>((const __half2*)bufH, bufF, rowptr, edges, dinvp, b2, n);

    // layer 3: 64 -> 40, no relu
    gemm_kernel<HID><<<gemmBlocks, 256>>>(bufF, W3, bufH, n, NCLS);
    agg_kernel<NCLS, false><<<aggBlocks, 256>>>((const __half2*)bufH, out, rowptr, edges, dinvp, b3, n);
}

// round 10
// speedup vs baseline: 1.0601x; 1.0348x over previous
#include <cuda_runtime.h>
#include <cuda_fp16.h>
#include <math.h>

// Problem constants (fixed by the dataset)
#define NNODES 50000
#define NEDGES 800000
#define INF    128
#define HID    64
#define NCLS   40

// ---------------- scratch (static __device__ globals; no allocation) -------
__device__ int    g_deg[NNODES];       // in-edge count (self loop excluded)
__device__ int    g_fill[NNODES];
__device__ int    g_rowptr[NNODES + 1];
__device__ float  g_dinv[NNODES];
__device__ int2   g_edge[NEDGES];                 // {src, __float_as_int(dinv[src])}
__device__ __half g_bufH[(size_t)NNODES * HID];   // GEMM outputs (fp16, gathered by agg)
__device__ float  g_bufF[(size_t)NNODES * HID];   // agg outputs (fp32, GEMM inputs)

// ---------------- graph preprocessing --------------------------------------

__global__ void hist_kernel(int* __restrict__ deg, const int* __restrict__ dst, int E) {
    int e = blockIdx.x * blockDim.x + threadIdx.x;
    if (e < E) atomicAdd(&deg[dst[e]], 1);
}

// Single-block exclusive scan of deg -> row_ptr, plus dinv = rsqrt(deg+1).
__global__ void scan_kernel(const int* __restrict__ deg, int* __restrict__ rowptr,
                            float* __restrict__ dinv, int n, int E) {
    __shared__ int ssum[1024];
    int tid = threadIdx.x;
    int chunk = (n + 1023) / 1024;
    int base = tid * chunk;

    int s = 0;
    for (int i = 0; i < chunk; i++) {
        int idx = base + i;
        if (idx < n) s += deg[idx];
    }
    ssum[tid] = s;
    __syncthreads();
    for (int off = 1; off < 1024; off <<= 1) {
        int v = (tid >= off) ? ssum[tid - off] : 0;
        __syncthreads();
        ssum[tid] += v;
        __syncthreads();
    }
    int run = (tid > 0) ? ssum[tid - 1] : 0;
    for (int i = 0; i < chunk; i++) {
        int idx = base + i;
        if (idx < n) {
            int c = deg[idx];
            rowptr[idx] = run;
            run += c;
            dinv[idx] = rsqrtf((float)(c + 1));   // +1 self loop
        }
    }
    if (tid == 0) rowptr[n] = E;
}

// Build CSR-by-dst; fold dinv[src] into the edge record so the per-layer agg
// never does a random dinv lookup.
__global__ void build_kernel(const int* __restrict__ src, const int* __restrict__ dst,
                             const int* __restrict__ rowptr, int* __restrict__ fill,
                             const float* __restrict__ dinv, int2* __restrict__ edges, int E) {
    int e = blockIdx.x * blockDim.x + threadIdx.x;
    if (e < E) {
        int d = dst[e];
        int s = src[e];
        int pos = rowptr[d] + atomicAdd(&fill[d], 1);
        edges[pos] = make_int2(s, __float_as_int(dinv[s]));
    }
}

// ---------------- dense GEMM: C[M,N] = A[M,K] @ W[K,N],  N <= 64 -----------
template <int K>
__global__ void gemm_kernel(const float* __restrict__ A, const float* __restrict__ W,
                            __half* __restrict__ C, int M, int N) {
    __shared__ float Ws[K][64];
    __shared__ float As[32][68];   // +4 pad keeps float4 alignment

    int tid = threadIdx.x;
    int rowBase = blockIdx.x * 64;

    for (int i = tid; i < K * 64; i += 256) {
        int k = i >> 6, c = i & 63;
        Ws[k][c] = (c < N) ? W[k * N + c] : 0.0f;
    }

    int tx = tid & 15;          // -> 4 output cols
    int ty = tid >> 4;          // -> 4 output rows
    float acc[4][4] = {};

    for (int k0 = 0; k0 < K; k0 += 32) {
        __syncthreads();
        #pragma unroll
        for (int i = tid; i < (64 * 32) / 4; i += 256) {
            int idx = i * 4;
            int r = idx >> 5;
            int kk = idx & 31;
            int grow = rowBase + r;
            float4 v = make_float4(0.f, 0.f, 0.f, 0.f);
            if (grow < M) v = *(const float4*)&A[(size_t)grow * K + k0 + kk];
            As[kk + 0][r] = v.x;
            As[kk + 1][r] = v.y;
            As[kk + 2][r] = v.z;
            As[kk + 3][r] = v.w;
        }
        __syncthreads();

        #pragma unroll
        for (int k = 0; k < 32; k++) {
            float4 a = *(const float4*)&As[k][ty * 4];
            float4 w = *(const float4*)&Ws[k0 + k][tx * 4];
            acc[0][0] += a.x * w.x; acc[0][1] += a.x * w.y; acc[0][2] += a.x * w.z; acc[0][3] += a.x * w.w;
            acc[1][0] += a.y * w.x; acc[1][1] += a.y * w.y; acc[1][2] += a.y * w.z; acc[1][3] += a.y * w.w;
            acc[2][0] += a.z * w.x; acc[2][1] += a.z * w.y; acc[2][2] += a.z * w.z; acc[2][3] += a.z * w.w;
            acc[3][0] += a.w * w.x; acc[3][1] += a.w * w.y; acc[3][2] += a.w * w.z; acc[3][3] += a.w * w.w;
        }
    }

    #pragma unroll
    for (int i = 0; i < 4; i++) {
        int r = rowBase + ty * 4 + i;
        int c0 = tx * 4;
        if (r < M && c0 < N) {
            __half2 h01 = __floats2half2_rn(acc[i][0], acc[i][1]);
            __half2 h23 = __floats2half2_rn(acc[i][2], acc[i][3]);
            *(__half2*)&C[(size_t)r * N + c0 + 0] = h01;
            *(__half2*)&C[(size_t)r * N + c0 + 2] = h23;
        }
    }
}

// ---------------- aggregation (gather, one warp per node) ------------------
// out[v] = dv * ( sum_{s in nbr(v)} dinv[s]*H[s]  +  dv*H[v] ) + bias
// Edge records are batch-loaded 32-at-a-time (coalesced, one int2 per lane)
// and broadcast via shuffles, so the inner loop is independent gathers only.
template <int F, bool RELU>
__global__ void agg_kernel(const __half2* __restrict__ H, float* __restrict__ out,
                           const int* __restrict__ rowptr, const int2* __restrict__ edges,
                           const float* __restrict__ dinv, const float* __restrict__ bias,
                           int n) {
    int w = (blockIdx.x * blockDim.x + threadIdx.x) >> 5;
    int lane = threadIdx.x & 31;
    if (w >= n) return;

    const bool act = lane < (F / 2);      // F=64: all lanes; F=40: lanes 0..19
    float ax = 0.f, ay = 0.f;
    int beg = rowptr[w];
    int end = rowptr[w + 1];
    float dv = dinv[w];

    for (int base = beg; base < end; base += 32) {
        int m = end - base;
        if (m > 32) m = 32;
        int2 my = make_int2(0, 0);
        if (base + lane < end) my = edges[base + lane];

        int j = 0;
        for (; j + 4 <= m; j += 4) {
            int   s0 = __shfl_sync(0xffffffffu, my.x, j + 0);
            int   s1 = __shfl_sync(0xffffffffu, my.x, j + 1);
            int   s2 = __shfl_sync(0xffffffffu, my.x, j + 2);
            int   s3 = __shfl_sync(0xffffffffu, my.x, j + 3);
            float w0 = __int_as_float(__shfl_sync(0xffffffffu, my.y, j + 0));
            float w1 = __int_as_float(__shfl_sync(0xffffffffu, my.y, j + 1));
            float w2 = __int_as_float(__shfl_sync(0xffffffffu, my.y, j + 2));
            float w3 = __int_as_float(__shfl_sync(0xffffffffu, my.y, j + 3));
            if (act) {
                float2 h0 = __half22float2(H[(size_t)s0 * (F / 2) + lane]);
                float2 h1 = __half22float2(H[(size_t)s1 * (F / 2) + lane]);
                float2 h2 = __half22float2(H[(size_t)s2 * (F / 2) + lane]);
                float2 h3 = __half22float2(H[(size_t)s3 * (F / 2) + lane]);
                ax += w0 * h0.x + w1 * h1.x;
                ay += w0 * h0.y + w1 * h1.y;
                ax += w2 * h2.x + w3 * h3.x;
                ay += w2 * h2.y + w3 * h3.y;
            }
        }
        for (; j < m; j++) {
            int   s0 = __shfl_sync(0xffffffffu, my.x, j);
            float w0 = __int_as_float(__shfl_sync(0xffffffffu, my.y, j));
            if (act) {
                float2 h0 = __half22float2(H[(size_t)s0 * (F / 2) + lane]);
                ax += w0 * h0.x;
                ay += w0 * h0.y;
            }
        }
    }

    if (act) {
        // self loop
        float2 hv = __half22float2(H[(size_t)w * (F / 2) + lane]);
        ax += dv * hv.x;
        ay += dv * hv.y;
        float o0 = dv * ax + bias[lane * 2 + 0];
        float o1 = dv * ay + bias[lane * 2 + 1];
        if (RELU) { o0 = fmaxf(o0, 0.f); o1 = fmaxf(o1, 0.f); }
        *(float2*)&out[(size_t)w * F + lane * 2] = make_float2(o0, o1);
    }
}

// ---------------- launcher --------------------------------------------------

extern "C" void kernel_launch(void* const* d_in, const int* in_sizes, int n_in,
                              void* d_out, int out_size) {
    const float* x  = (const float*)d_in[0];
    const int*   ei = (const int*)d_in[1];
    const float* W1 = (const float*)d_in[2];
    const float* b1 = (const float*)d_in[3];
    const float* W2 = (const float*)d_in[4];
    const float* b2 = (const float*)d_in[5];
    const float* W3 = (const float*)d_in[6];
    const float* b3 = (const float*)d_in[7];
    float* out = (float*)d_out;

    const int n = in_sizes[0] / INF;     // 50000
    const int E = in_sizes[1] / 2;       // 800000

    int *deg, *fill, *rowptr;
    int2* edges;
    float *dinvp, *bufF;
    __half* bufH;
    cudaGetSymbolAddress((void**)&deg,    g_deg);
    cudaGetSymbolAddress((void**)&fill,   g_fill);
    cudaGetSymbolAddress((void**)&rowptr, g_rowptr);
    cudaGetSymbolAddress((void**)&edges,  g_edge);
    cudaGetSymbolAddress((void**)&dinvp,  g_dinv);
    cudaGetSymbolAddress((void**)&bufH,   g_bufH);
    cudaGetSymbolAddress((void**)&bufF,   g_bufF);

    const int* srcp = ei;
    const int* dstp = ei + E;

    // Side stream + events, created once on first (non-capture) call.
    static cudaStream_t s_side = nullptr;
    static cudaEvent_t  ev_fork = nullptr, ev_join = nullptr;
    if (!s_side) {
        cudaStreamCreateWithFlags(&s_side, cudaStreamNonBlocking);
        cudaEventCreateWithFlags(&ev_fork, cudaEventDisableTiming);
        cudaEventCreateWithFlags(&ev_join, cudaEventDisableTiming);
    }

    const int gemmBlocks = (n + 63) / 64;
    const int aggBlocks  = (n * 32 + 255) / 256;

    // Fork: gemm1 depends only on x/W1 -> run it concurrently with the
    // graph preprocessing chain on a side stream.
    cudaEventRecord(ev_fork, (cudaStream_t)0);
    cudaStreamWaitEvent(s_side, ev_fork, 0);
    gemm_kernel<INF><<<gemmBlocks, 256, 0, s_side>>>(x, W1, bufH, n, HID);
    cudaEventRecord(ev_join, s_side);

    // Preprocessing on the main (legacy) stream, overlapped with gemm1.
    cudaMemsetAsync(deg,  0, (size_t)n * sizeof(int));
    cudaMemsetAsync(fill, 0, (size_t)n * sizeof(int));
    hist_kernel<<<(E + 255) / 256, 256>>>(deg, dstp, E);
    scan_kernel<<<1, 1024>>>(deg, rowptr, dinvp, n, E);
    build_kernel<<<(E + 255) / 256, 256>>>(srcp, dstp, rowptr, fill, dinvp, edges, E);

    // Join before agg1 (needs both bufH and the CSR).
    cudaStreamWaitEvent((cudaStream_t)0, ev_join, 0);

    // layer 1: 128 -> 64, relu
    agg_kernel<HID, true><<<aggBlocks, 256>>>((const __half2*)bufH, bufF, rowptr, edges, dinvp, b1, n);

    // layer 2: 64 -> 64, relu
    gemm_kernel<HID><<<gemmBlocks, 256>>>(bufF, W2, bufH, n, HID);
    agg_kernel<HID, true><<<aggBlocks, 256>>>((const __half2*)bufH, bufF, rowptr, edges, dinvp, b2, n);

    // layer 3: 64 -> 40, no relu
    gemm_kernel<HID><<<gemmBlocks, 256>>>(bufF, W3, bufH, n, NCLS);
    agg_kernel<NCLS, false><<<aggBlocks, 256>>>((const __half2*)bufH, out, rowptr, edges, dinvp, b3, n);
}

// round 14
// speedup vs baseline: 1.1003x; 1.0379x over previous
#include <cuda_runtime.h>
#include <cuda_fp16.h>
#include <math.h>

// Problem constants (fixed by the dataset)
#define NNODES 50000
#define NEDGES 800000
#define INF    128
#define HID    64
#define NCLS   40

// ---------------- scratch (static __device__ globals; no allocation) -------
__device__ int    g_deg[NNODES];       // in-edge count (self loop excluded)
__device__ int    g_fill[NNODES];
__device__ int    g_rowptr[NNODES + 1];
__device__ float  g_dinv[NNODES];
__device__ int2   g_edge[NEDGES];                 // {src, __float_as_int(dinv[src])}
__device__ __half g_bufH[(size_t)NNODES * HID];   // GEMM outputs (fp16, gathered by agg)
__device__ float  g_bufF[(size_t)NNODES * HID];   // agg outputs (fp32, GEMM inputs)

// ---------------- graph preprocessing --------------------------------------

__global__ void hist_kernel(int* __restrict__ deg, const int* __restrict__ dst, int E) {
    int i = blockIdx.x * blockDim.x + threadIdx.x;
    int e = i * 4;
    if (e + 3 < E) {
        int4 d = *(const int4*)(dst + e);
        atomicAdd(&deg[d.x], 1);
        atomicAdd(&deg[d.y], 1);
        atomicAdd(&deg[d.z], 1);
        atomicAdd(&deg[d.w], 1);
    } else {
        for (; e < E; e++) atomicAdd(&deg[dst[e]], 1);
    }
}

// Single-block exclusive scan of deg -> row_ptr, plus dinv = rsqrt(deg+1).
__global__ void scan_kernel(const int* __restrict__ deg, int* __restrict__ rowptr,
                            float* __restrict__ dinv, int n, int E) {
    __shared__ int ssum[1024];
    int tid = threadIdx.x;
    int chunk = (n + 1023) / 1024;
    int base = tid * chunk;

    int s = 0;
    for (int i = 0; i < chunk; i++) {
        int idx = base + i;
        if (idx < n) s += deg[idx];
    }
    ssum[tid] = s;
    __syncthreads();
    for (int off = 1; off < 1024; off <<= 1) {
        int v = (tid >= off) ? ssum[tid - off] : 0;
        __syncthreads();
        ssum[tid] += v;
        __syncthreads();
    }
    int run = (tid > 0) ? ssum[tid - 1] : 0;
    for (int i = 0; i < chunk; i++) {
        int idx = base + i;
        if (idx < n) {
            int c = deg[idx];
            rowptr[idx] = run;
            run += c;
            dinv[idx] = rsqrtf((float)(c + 1));   // +1 self loop
        }
    }
    if (tid == 0) rowptr[n] = E;
}

// Build CSR-by-dst; fold dinv[src] into the edge record so the per-layer agg
// never does a random dinv lookup.
__global__ void build_kernel(const int* __restrict__ src, const int* __restrict__ dst,
                             const int* __restrict__ rowptr, int* __restrict__ fill,
                             const float* __restrict__ dinv, int2* __restrict__ edges, int E) {
    int e = blockIdx.x * blockDim.x + threadIdx.x;
    if (e < E) {
        int d = dst[e];
        int s = src[e];
        int pos = rowptr[d] + atomicAdd(&fill[d], 1);
        edges[pos] = make_int2(s, __float_as_int(dinv[s]));
    }
}

// ---------------- dense GEMM: C[M,N] = A[M,K] @ W[K,N],  N <= 64 -----------
template <int K>
__global__ void gemm_kernel(const float* __restrict__ A, const float* __restrict__ W,
                            __half* __restrict__ C, int M, int N) {
    __shared__ float Ws[K][64];
    __shared__ float As[32][68];   // +4 pad keeps float4 alignment

    int tid = threadIdx.x;
    int rowBase = blockIdx.x * 64;

    for (int i = tid; i < K * 64; i += 256) {
        int k = i >> 6, c = i & 63;
        Ws[k][c] = (c < N) ? W[k * N + c] : 0.0f;
    }

    int tx = tid & 15;          // -> 4 output cols
    int ty = tid >> 4;          // -> 4 output rows
    float acc[4][4] = {};

    for (int k0 = 0; k0 < K; k0 += 32) {
        __syncthreads();
        #pragma unroll
        for (int i = tid; i < (64 * 32) / 4; i += 256) {
            int idx = i * 4;
            int r = idx >> 5;
            int kk = idx & 31;
            int grow = rowBase + r;
            float4 v = make_float4(0.f, 0.f, 0.f, 0.f);
            if (grow < M) v = *(const float4*)&A[(size_t)grow * K + k0 + kk];
            As[kk + 0][r] = v.x;
            As[kk + 1][r] = v.y;
            As[kk + 2][r] = v.z;
            As[kk + 3][r] = v.w;
        }
        __syncthreads();

        #pragma unroll
        for (int k = 0; k < 32; k++) {
            float4 a = *(const float4*)&As[k][ty * 4];
            float4 w = *(const float4*)&Ws[k0 + k][tx * 4];
            acc[0][0] += a.x * w.x; acc[0][1] += a.x * w.y; acc[0][2] += a.x * w.z; acc[0][3] += a.x * w.w;
            acc[1][0] += a.y * w.x; acc[1][1] += a.y * w.y; acc[1][2] += a.y * w.z; acc[1][3] += a.y * w.w;
            acc[2][0] += a.z * w.x; acc[2][1] += a.z * w.y; acc[2][2] += a.z * w.z; acc[2][3] += a.z * w.w;
            acc[3][0] += a.w * w.x; acc[3][1] += a.w * w.y; acc[3][2] += a.w * w.z; acc[3][3] += a.w * w.w;
        }
    }

    #pragma unroll
    for (int i = 0; i < 4; i++) {
        int r = rowBase + ty * 4 + i;
        int c0 = tx * 4;
        if (r < M && c0 < N) {
            __half2 h01 = __floats2half2_rn(acc[i][0], acc[i][1]);
            __half2 h23 = __floats2half2_rn(acc[i][2], acc[i][3]);
            *(__half2*)&C[(size_t)r * N + c0 + 0] = h01;
            *(__half2*)&C[(size_t)r * N + c0 + 2] = h23;
        }
    }
}

// ---------------- aggregation v3: 4 edges in flight per warp ----------------
// out[v] = dv * ( sum_{s in nbr(v)} dinv[s]*H[s]  +  dv*H[v] ) + bias
// Warp = 4 groups x 8 lanes. Each lane gathers uint4 (8 fp16 feats), so one
// warp-LDG fetches 4 DIFFERENT source rows (one per group). Edge records are
// batch-loaded 32-wide and distributed via 2 shuffles per 4 edges. Final
// cross-group combine: 16x shfl_xor.
template <int F, bool RELU>
__global__ void agg_kernel(const __half* __restrict__ H, float* __restrict__ out,
                           const int* __restrict__ rowptr, const int2* __restrict__ edges,
                           const float* __restrict__ dinv, const float* __restrict__ bias,
                           int n) {
    constexpr int LPR = (F + 7) / 8;     // active lanes per group (64->8, 40->5)
    int w = (blockIdx.x * blockDim.x + threadIdx.x) >> 5;
    int lane = threadIdx.x & 31;
    if (w >= n) return;
    int g = lane >> 3;                   // edge slot within a quad
    int l = lane & 7;                    // feature slice: feats [8l, 8l+8)
    const bool act = l < LPR;

    float2 a0 = make_float2(0.f, 0.f), a1 = make_float2(0.f, 0.f);
    float2 a2 = make_float2(0.f, 0.f), a3 = make_float2(0.f, 0.f);
    int beg = rowptr[w];
    int end = rowptr[w + 1];
    float dv = dinv[w];

    for (int base = beg; base < end; base += 32) {
        int m = end - base;
        if (m > 32) m = 32;
        int2 my = make_int2(0, 0);
        if (base + lane < end) my = edges[base + lane];

        #pragma unroll
        for (int t = 0; t < 8; t++) {
            if (4 * t >= m) break;                       // warp-uniform
            int j = 4 * t + g;
            int   s  = __shfl_sync(0xffffffffu, my.x, j);
            float wt = __int_as_float(__shfl_sync(0xffffffffu, my.y, j));
            if (j < m && act) {
                uint4 v = *(const uint4*)(H + (size_t)s * F + l * 8);
                float2 h0 = __half22float2(*(__half2*)&v.x);
                float2 h1 = __half22float2(*(__half2*)&v.y);
                float2 h2 = __half22float2(*(__half2*)&v.z);
                float2 h3 = __half22float2(*(__half2*)&v.w);
                a0.x += wt * h0.x; a0.y += wt * h0.y;
                a1.x += wt * h1.x; a1.y += wt * h1.y;
                a2.x += wt * h2.x; a2.y += wt * h2.y;
                a3.x += wt * h3.x; a3.y += wt * h3.y;
            }
        }
    }

    // combine the 4 groups (same feature slice lives at lanes l, l+8, l+16, l+24)
    #pragma unroll
    for (int off = 8; off <= 16; off <<= 1) {
        a0.x += __shfl_xor_sync(0xffffffffu, a0.x, off);
        a0.y += __shfl_xor_sync(0xffffffffu, a0.y, off);
        a1.x += __shfl_xor_sync(0xffffffffu, a1.x, off);
        a1.y += __shfl_xor_sync(0xffffffffu, a1.y, off);
        a2.x += __shfl_xor_sync(0xffffffffu, a2.x, off);
        a2.y += __shfl_xor_sync(0xffffffffu, a2.y, off);
        a3.x += __shfl_xor_sync(0xffffffffu, a3.x, off);
        a3.y += __shfl_xor_sync(0xffffffffu, a3.y, off);
    }

    if (act) {
        // self loop
        uint4 v = *(const uint4*)(H + (size_t)w * F + l * 8);
        float2 h0 = __half22float2(*(__half2*)&v.x);
        float2 h1 = __half22float2(*(__half2*)&v.y);
        float2 h2 = __half22float2(*(__half2*)&v.z);
        float2 h3 = __half22float2(*(__half2*)&v.w);
        a0.x += dv * h0.x; a0.y += dv * h0.y;
        a1.x += dv * h1.x; a1.y += dv * h1.y;
        a2.x += dv * h2.x; a2.y += dv * h2.y;
        a3.x += dv * h3.x; a3.y += dv * h3.y;

        float4 bA = *(const float4*)(bias + l * 8);
        float4 bB = *(const float4*)(bias + l * 8 + 4);
        float4 o0, o1;
        o0.x = dv * a0.x + bA.x;  o0.y = dv * a0.y + bA.y;
        o0.z = dv * a1.x + bA.z;  o0.w = dv * a1.y + bA.w;
        o1.x = dv * a2.x + bB.x;  o1.y = dv * a2.y + bB.y;
        o1.z = dv * a3.x + bB.z;  o1.w = dv * a3.y + bB.w;
        if (RELU) {
            o0.x = fmaxf(o0.x, 0.f); o0.y = fmaxf(o0.y, 0.f);
            o0.z = fmaxf(o0.z, 0.f); o0.w = fmaxf(o0.w, 0.f);
            o1.x = fmaxf(o1.x, 0.f); o1.y = fmaxf(o1.y, 0.f);
            o1.z = fmaxf(o1.z, 0.f); o1.w = fmaxf(o1.w, 0.f);
        }
        if (g == 0) {   // one group writes the combined result
            *(float4*)(out + (size_t)w * F + l * 8)     = o0;
            *(float4*)(out + (size_t)w * F + l * 8 + 4) = o1;
        }
    }
}

// ---------------- launcher --------------------------------------------------

extern "C" void kernel_launch(void* const* d_in, const int* in_sizes, int n_in,
                              void* d_out, int out_size) {
    const float* x  = (const float*)d_in[0];
    const int*   ei = (const int*)d_in[1];
    const float* W1 = (const float*)d_in[2];
    const float* b1 = (const float*)d_in[3];
    const float* W2 = (const float*)d_in[4];
    const float* b2 = (const float*)d_in[5];
    const float* W3 = (const float*)d_in[6];
    const float* b3 = (const float*)d_in[7];
    float* out = (float*)d_out;

    const int n = in_sizes[0] / INF;     // 50000
    const int E = in_sizes[1] / 2;       // 800000

    int *deg, *fill, *rowptr;
    int2* edges;
    float *dinvp, *bufF;
    __half* bufH;
    cudaGetSymbolAddress((void**)&deg,    g_deg);
    cudaGetSymbolAddress((void**)&fill,   g_fill);
    cudaGetSymbolAddress((void**)&rowptr, g_rowptr);
    cudaGetSymbolAddress((void**)&edges,  g_edge);
    cudaGetSymbolAddress((void**)&dinvp,  g_dinv);
    cudaGetSymbolAddress((void**)&bufH,   g_bufH);
    cudaGetSymbolAddress((void**)&bufF,   g_bufF);

    const int* srcp = ei;
    const int* dstp = ei + E;

    // Side stream + events, created once on first (non-capture) call.
    static cudaStream_t s_side = nullptr;
    static cudaEvent_t  ev_fork = nullptr, ev_join = nullptr;
    if (!s_side) {
        cudaStreamCreateWithFlags(&s_side, cudaStreamNonBlocking);
        cudaEventCreateWithFlags(&ev_fork, cudaEventDisableTiming);
        cudaEventCreateWithFlags(&ev_join, cudaEventDisableTiming);
    }

    const int gemmBlocks = (n + 63) / 64;
    const int aggBlocks  = (n * 32 + 255) / 256;

    // Fork: gemm1 depends only on x/W1 -> run it concurrently with the
    // graph preprocessing chain on a side stream.
    cudaEventRecord(ev_fork, (cudaStream_t)0);
    cudaStreamWaitEvent(s_side, ev_fork, 0);
    gemm_kernel<INF><<<gemmBlocks, 256, 0, s_side>>>(x, W1, bufH, n, HID);
    cudaEventRecord(ev_join, s_side);

    // Preprocessing on the main (legacy) stream, overlapped with gemm1.
    cudaMemsetAsync(deg,  0, (size_t)n * sizeof(int));
    cudaMemsetAsync(fill, 0, (size_t)n * sizeof(int));
    hist_kernel<<<(E / 4 + 255) / 256, 256>>>(deg, dstp, E);
    scan_kernel<<<1, 1024>>>(deg, rowptr, dinvp, n, E);
    build_kernel<<<(E + 255) / 256, 256>>>(srcp, dstp, rowptr, fill, dinvp, edges, E);

    // Join before agg1 (needs both bufH and the CSR).
    cudaStreamWaitEvent((cudaStream_t)0, ev_join, 0);

    // layer 1: 128 -> 64, relu
    agg_kernel<HID, true><<<aggBlocks, 256>>>(bufH, bufF, rowptr, edges, dinvp, b1, n);

    // layer 2: 64 -> 64, relu
    gemm_kernel<HID><<<gemmBlocks, 256>>>(bufF, W2, bufH, n, HID);
    agg_kernel<HID, true><<<aggBlocks, 256>>>(bufH, bufF, rowptr, edges, dinvp, b2, n);

    // layer 3: 64 -> 40, no relu
    gemm_kernel<HID><<<gemmBlocks, 256>>>(bufF, W3, bufH, n, NCLS);
    agg_kernel<NCLS, false><<<aggBlocks, 256>>>(bufH, out, rowptr, edges, dinvp, b3, n);
}